// round 8
// baseline (speedup 1.0000x reference)
#include <cuda_runtime.h>
#include <math.h>
#include <stdint.h>

#define BC 8
#define NC 4096
#define CC 768
#define HC 12
#define DC 64
#define MC 64
#define BHC (BC*HC)
#define NSPL 8

__device__ float g_Q[(size_t)BHC*NC*DC];
__device__ float g_K[(size_t)BHC*NC*DC];
__device__ float g_V[(size_t)BHC*NC*DC];
__device__ float g_Kl[(size_t)BHC*MC*DC];
__device__ float g_Ql[(size_t)BHC*MC*DC];
__device__ float g_inv[(size_t)BHC*MC*MC];
__device__ float g_W[(size_t)BHC*MC*DC];
__device__ float g_SV[(size_t)BC*NC*CC];
__device__ float g_pacc[(size_t)BHC*NSPL*MC*DC];
__device__ float g_psum[BHC*NSPL*MC];

// ===================== helpers =====================
__device__ __forceinline__ uint32_t smem_u32(const void* p) {
    uint32_t a;
    asm("{ .reg .u64 t; cvta.to.shared.u64 t, %1; cvt.u32.u64 %0, t; }" : "=r"(a) : "l"(p));
    return a;
}
__device__ __forceinline__ uint32_t f2tf(float f) {
    uint32_t u;
    asm("cvt.rna.tf32.f32 %0, %1;" : "=r"(u) : "f"(f));
    return u;
}
__device__ __forceinline__ void mma_tf32(float* c, const uint32_t* a, const uint32_t* b) {
    asm volatile(
        "mma.sync.aligned.m16n8k8.row.col.f32.tf32.tf32.f32 "
        "{%0,%1,%2,%3}, {%4,%5,%6,%7}, {%8,%9}, {%0,%1,%2,%3};"
        : "+f"(c[0]), "+f"(c[1]), "+f"(c[2]), "+f"(c[3])
        : "r"(a[0]), "r"(a[1]), "r"(a[2]), "r"(a[3]), "r"(b[0]), "r"(b[1]));
}
__device__ __forceinline__ void cp16(uint32_t s, const void* g) {
    asm volatile("cp.async.cg.shared.global [%0], [%1], 16;" :: "r"(s), "l"(g));
}

// ============ mma.sync tf32 GEMM: C[128x128] = A * B^T ====================
template<int EPI>
__global__ void __launch_bounds__(256) mma_gemm(
    const float* __restrict__ A, const float* __restrict__ Bm,
    float* __restrict__ out, const float* __restrict__ bias)
{
    extern __shared__ float gs[];
    const float* Abase = (EPI == 1) ? (const float*)g_SV : A;
    int tid = threadIdx.x, lane = tid & 31, wid = tid >> 5;
    int warp_m = wid & 3, warp_n = wid >> 2;
    int n0 = blockIdx.x * 128, m0 = blockIdx.y * 128;
    const float* Ap = Abase + (size_t)m0 * 768;
    const float* Bp = Bm + (size_t)n0 * 768;
    uint32_t sbase = smem_u32(gs);

    float acc[2][8][4];
#pragma unroll
    for (int mt = 0; mt < 2; mt++)
#pragma unroll
        for (int nt = 0; nt < 8; nt++)
#pragma unroll
            for (int u = 0; u < 4; u++) acc[mt][nt][u] = 0.f;

    int prow = tid >> 3, pkg = (tid & 7) * 4;
#define PREFETCH(c, bi) {                                                   \
        int k0 = (c) * 32;                                                  \
        uint32_t ao = sbase + (uint32_t)(bi) * 36864u;                      \
        uint32_t bo = ao + 18432u;                                          \
        _Pragma("unroll")                                                   \
        for (int p = 0; p < 4; p++) {                                       \
            int row = prow + p * 32;                                        \
            uint32_t so = (uint32_t)(row * 36 + pkg) * 4u;                  \
            cp16(ao + so, Ap + (size_t)row * 768 + k0 + pkg);               \
            cp16(bo + so, Bp + (size_t)row * 768 + k0 + pkg);               \
        }                                                                   \
        asm volatile("cp.async.commit_group;" ::: "memory");                \
    }

    PREFETCH(0, 0);
    int gid = lane >> 2, tig = lane & 3;
    for (int c = 0; c < 24; c++) {
        int bi = c & 1;
        asm volatile("cp.async.wait_group 0;" ::: "memory");
        __syncthreads();
        if (c + 1 < 24) PREFETCH(c + 1, bi ^ 1);
        const float* As = gs + bi * 9216;
        const float* Bs = As + 4608;
#pragma unroll
        for (int ks = 0; ks < 4; ks++) {
            int kb = ks * 8 + tig;
            uint32_t af[2][4], bf[8][2];
#pragma unroll
            for (int mt = 0; mt < 2; mt++) {
                int r0 = warp_m * 32 + mt * 16 + gid;
                af[mt][0] = f2tf(As[r0 * 36 + kb]);
                af[mt][1] = f2tf(As[(r0 + 8) * 36 + kb]);
                af[mt][2] = f2tf(As[r0 * 36 + kb + 4]);
                af[mt][3] = f2tf(As[(r0 + 8) * 36 + kb + 4]);
            }
#pragma unroll
            for (int nt = 0; nt < 8; nt++) {
                int c0 = warp_n * 64 + nt * 8 + gid;
                bf[nt][0] = f2tf(Bs[c0 * 36 + kb]);
                bf[nt][1] = f2tf(Bs[c0 * 36 + kb + 4]);
            }
#pragma unroll
            for (int mt = 0; mt < 2; mt++)
#pragma unroll
                for (int nt = 0; nt < 8; nt++)
                    mma_tf32(acc[mt][nt], af[mt], bf[nt]);
        }
        __syncthreads();
    }

#pragma unroll
    for (int mt = 0; mt < 2; mt++)
#pragma unroll
        for (int nt = 0; nt < 8; nt++) {
            int r = warp_m * 32 + mt * 16 + gid;
            int col = warp_n * 64 + nt * 8 + tig * 2;
            *(float2*)(gs + r * 130 + col) = make_float2(acc[mt][nt][0], acc[mt][nt][1]);
            *(float2*)(gs + (r + 8) * 130 + col) = make_float2(acc[mt][nt][2], acc[mt][nt][3]);
        }
    __syncthreads();

    if (EPI == 0) {
        int g = n0 / 768, nb = n0 - g * 768;
        for (int e = tid; e < 16384; e += 256) {
            int row = e >> 7, col = e & 127;
            int r = m0 + row, bb = r >> 12, nn = r & (NC - 1);
            int rem = nb + col, h = rem >> 6, d = rem & 63;
            size_t off = (((size_t)bb * HC + h) * NC + nn) * DC + d;
            float v = gs[row * 130 + col];
            if (g == 0) g_Q[off] = v * 0.125f;
            else if (g == 1) g_K[off] = v;
            else g_V[off] = v;
        }
    } else {
        for (int e = tid; e < 16384; e += 256) {
            int row = e >> 7, col = e & 127;
            int r = m0 + row, c2 = n0 + col;
            int bb = r >> 12, nn = r & (NC - 1);
            int h = c2 >> 6, d = c2 & 63;
            out[(size_t)r * 768 + c2] = gs[row * 130 + col] + bias[c2]
                + g_V[(((size_t)bb * HC + h) * NC + nn) * DC + d];
        }
    }
#undef PREFETCH
}

// ===================== landmarks =====================
__global__ void __launch_bounds__(64) landmarks_kernel()
{
    int bhm = blockIdx.x;
    int bh = bhm >> 6, m = bhm & 63;
    int d = threadIdx.x;
    size_t base = ((size_t)bh * NC + m * 64) * DC + d;
    float sk = 0.f, sq = 0.f;
#pragma unroll 8
    for (int i = 0; i < 64; i++) {
        sk += g_K[base + (size_t)i * DC];
        sq += g_Q[base + (size_t)i * DC];
    }
    size_t o = ((size_t)bh * MC + m) * DC + d;
    g_Kl[o] = sk * (1.0f / 64.0f);
    g_Ql[o] = sq * (1.0f / 64.0f);
}

// ===================== kernel2 softmax + Newton-Schulz =====================
__device__ __forceinline__ void mm64(float* __restrict__ dst, const float* __restrict__ X,
                                     const float* __restrict__ Y, int tid, float scale)
{
    __syncthreads();
    int i = tid >> 2, q = tid & 3;
    float a[16];
#pragma unroll
    for (int j = 0; j < 16; j++) a[j] = 0.f;
    const float* Xi = X + i * 64;
#pragma unroll
    for (int k = 0; k < 64; k += 4) {
        float4 xv = *(const float4*)(Xi + k);
        float xs[4] = {xv.x, xv.y, xv.z, xv.w};
#pragma unroll
        for (int kk = 0; kk < 4; kk++) {
            const float* Yr = Y + (k + kk) * 64 + q * 16;
            float4 y0 = *(const float4*)(Yr);
            float4 y1 = *(const float4*)(Yr + 4);
            float4 y2 = *(const float4*)(Yr + 8);
            float4 y3 = *(const float4*)(Yr + 12);
            float xk = xs[kk];
            a[0]  = fmaf(xk, y0.x, a[0]);  a[1]  = fmaf(xk, y0.y, a[1]);
            a[2]  = fmaf(xk, y0.z, a[2]);  a[3]  = fmaf(xk, y0.w, a[3]);
            a[4]  = fmaf(xk, y1.x, a[4]);  a[5]  = fmaf(xk, y1.y, a[5]);
            a[6]  = fmaf(xk, y1.z, a[6]);  a[7]  = fmaf(xk, y1.w, a[7]);
            a[8]  = fmaf(xk, y2.x, a[8]);  a[9]  = fmaf(xk, y2.y, a[9]);
            a[10] = fmaf(xk, y2.z, a[10]); a[11] = fmaf(xk, y2.w, a[11]);
            a[12] = fmaf(xk, y3.x, a[12]); a[13] = fmaf(xk, y3.y, a[13]);
            a[14] = fmaf(xk, y3.z, a[14]); a[15] = fmaf(xk, y3.w, a[15]);
        }
    }
    float* Di = dst + i * 64 + q * 16;
#pragma unroll
    for (int j = 0; j < 16; j += 4) {
        float4 w = { a[j]*scale, a[j+1]*scale, a[j+2]*scale, a[j+3]*scale };
        *(float4*)(Di + j) = w;
    }
    __syncthreads();
}
__device__ __forceinline__ void cIminus(float* __restrict__ dst, float cv,
                                        const float* __restrict__ A, int tid)
{
    for (int e = tid; e < 4096; e += 256) {
        int i = e >> 6, j = e & 63;
        dst[e] = (i == j ? cv : 0.0f) - A[e];
    }
    __syncthreads();
}
__global__ void __launch_bounds__(256) inv_kernel()
{
    extern __shared__ float sm[];
    float* Ks = sm;
    float* bufs[4] = { sm + 4096, sm + 2*4096, sm + 3*4096, sm + 4*4096 };
    __shared__ float cs[64];
    int bh = blockIdx.x, tid = threadIdx.x;
    size_t lb = (size_t)bh * 4096;

    for (int e = tid * 4; e < 4096; e += 1024) {
        *(float4*)(bufs[2] + e) = *(const float4*)(g_Ql + lb + e);
        *(float4*)(bufs[3] + e) = *(const float4*)(g_Kl + lb + e);
    }
    __syncthreads();
    {
        int m = tid >> 2, q = tid & 3;
        float s[16];
        const float* qm = bufs[2] + m * 64;
#pragma unroll
        for (int j = 0; j < 16; j++) {
            const float* kl = bufs[3] + (q * 16 + j) * 64;
            float a = 0.f;
#pragma unroll
            for (int d = 0; d < 64; d += 4) {
                float4 qv = *(const float4*)(qm + d);
                float4 kv = *(const float4*)(kl + d);
                a = fmaf(qv.x, kv.x, a); a = fmaf(qv.y, kv.y, a);
                a = fmaf(qv.z, kv.z, a); a = fmaf(qv.w, kv.w, a);
            }
            s[j] = a;
        }
        float sum = 0.f;
#pragma unroll
        for (int j = 0; j < 16; j++) { s[j] = __expf(s[j]); sum += s[j]; }
        sum += __shfl_xor_sync(~0u, sum, 1);
        sum += __shfl_xor_sync(~0u, sum, 2);
        float is = 1.0f / sum;
#pragma unroll
        for (int j = 0; j < 16; j++) Ks[m * 64 + q * 16 + j] = s[j] * is;
    }
    __syncthreads();
    if (tid < 64) {
        float a = 0.f;
        for (int i = 0; i < 64; i++) a += Ks[i * 64 + tid];
        cs[tid] = a;
    }
    __syncthreads();
    float sc = cs[0];
    for (int j = 1; j < 64; j++) sc = fmaxf(sc, cs[j]);
    float rs = 1.0f / sc;
    for (int e = tid; e < 4096; e += 256) {
        int i = e >> 6, j = e & 63;
        bufs[0][e] = Ks[j * 64 + i] * rs;
    }
    __syncthreads();
    int vi = 0;
#pragma unroll 1
    for (int it = 0; it < 6; ++it) {
        float* pv = bufs[vi];
        float* f1 = bufs[(vi + 1) & 3];
        float* f2 = bufs[(vi + 2) & 3];
        float* f3 = bufs[(vi + 3) & 3];
        mm64(f1, Ks, pv, tid, 1.0f);
        cIminus(f2, 7.0f, f1, tid);
        mm64(f3, f1, f2, tid, 1.0f);
        cIminus(f2, 15.0f, f3, tid);
        mm64(f3, f1, f2, tid, 1.0f);
        cIminus(f2, 13.0f, f3, tid);
        mm64(f3, pv, f2, tid, 0.25f);
        vi = (vi + 3) & 3;
    }
    __syncthreads();
    float* pv = bufs[vi];
    for (int e = tid * 4; e < 4096; e += 1024)
        *(float4*)(g_inv + lb + e) = *(const float4*)(pv + e);
}

// ======= kernel3 part: exp(Ql·K^T)·V over 8 tiles (no-max, scores tiny) ====
// smem 51200B: Qls[4352] | Kt/Ps alias [4352] | Vt[4096]
__global__ void __launch_bounds__(256) k3v_part()
{
    extern __shared__ float s[];
    float* Qls = s;             // [d][m] stride 68
    float* Kt  = s + 4352;      // [d][n] stride 68 (dead after scores)
    float* Ps  = s + 4352;      // [n][m] stride 68 (aliases Kt)
    float* Vt  = s + 8704;      // [n][d] stride 64
    int bh = blockIdx.x, sp = blockIdx.y, tid = threadIdx.x;
    int tm = tid >> 4, tn = tid & 15;
    size_t base = (size_t)bh * NC * DC;

    for (int f = tid; f < 1024; f += 256) {
        int n = f >> 4, dg = (f & 15) * 4;
        float4 v = *(const float4*)(g_Ql + (size_t)bh * 4096 + n * 64 + dg);
        Qls[(dg+0)*68+n] = v.x; Qls[(dg+1)*68+n] = v.y;
        Qls[(dg+2)*68+n] = v.z; Qls[(dg+3)*68+n] = v.w;
    }
    float o[4][4], gsum[4];
#pragma unroll
    for (int i = 0; i < 4; i++) {
        gsum[i] = 0.f;
#pragma unroll
        for (int j = 0; j < 4; j++) o[i][j] = 0.f;
    }

    int ntile = NC / 64 / NSPL;   // 8
    for (int t = sp * ntile; t < (sp + 1) * ntile; t++) {
        __syncthreads();          // prev PV done: Kt/Ps + Vt reusable
        for (int f = tid; f < 1024; f += 256) {
            int n = f >> 4, dg = (f & 15) * 4;
            float4 kv = *(const float4*)(g_K + base + (size_t)t * 4096 + n * 64 + dg);
            Kt[(dg+0)*68+n] = kv.x; Kt[(dg+1)*68+n] = kv.y;
            Kt[(dg+2)*68+n] = kv.z; Kt[(dg+3)*68+n] = kv.w;
            *(float4*)(Vt + n * 64 + dg) =
                *(const float4*)(g_V + base + (size_t)t * 4096 + n * 64 + dg);
        }
        __syncthreads();

        float sc[4][4];
#pragma unroll
        for (int i = 0; i < 4; i++)
#pragma unroll
            for (int j = 0; j < 4; j++) sc[i][j] = 0.f;
#pragma unroll 8
        for (int d = 0; d < 64; d++) {
            float4 q = *(const float4*)(Qls + d * 68 + tm * 4);
            float4 k = *(const float4*)(Kt + d * 68 + tn * 4);
            float qa[4] = {q.x, q.y, q.z, q.w};
            float ka[4] = {k.x, k.y, k.z, k.w};
#pragma unroll
            for (int i = 0; i < 4; i++)
#pragma unroll
                for (int j = 0; j < 4; j++) sc[i][j] = fmaf(qa[i], ka[j], sc[i][j]);
        }
        __syncthreads();          // everyone done reading Kt
#pragma unroll
        for (int i = 0; i < 4; i++) {
#pragma unroll
            for (int j = 0; j < 4; j++) {
                float p = __expf(sc[i][j]);
                Ps[(tn * 4 + j) * 68 + tm * 4 + i] = p;
                gsum[i] += p;
            }
        }
        __syncthreads();          // Ps visible
#pragma unroll 8
        for (int n = 0; n < 64; n++) {
            float4 p = *(const float4*)(Ps + n * 68 + tm * 4);
            float4 v = *(const float4*)(Vt + n * 64 + tn * 4);
            float pa[4] = {p.x, p.y, p.z, p.w};
            float va[4] = {v.x, v.y, v.z, v.w};
#pragma unroll
            for (int i = 0; i < 4; i++)
#pragma unroll
                for (int j = 0; j < 4; j++) o[i][j] = fmaf(pa[i], va[j], o[i][j]);
        }
    }
#pragma unroll
    for (int i = 0; i < 4; i++) {
        gsum[i] += __shfl_xor_sync(~0u, gsum[i], 1);
        gsum[i] += __shfl_xor_sync(~0u, gsum[i], 2);
        gsum[i] += __shfl_xor_sync(~0u, gsum[i], 4);
        gsum[i] += __shfl_xor_sync(~0u, gsum[i], 8);
    }
    size_t pb = ((size_t)bh * NSPL + sp) * 4096;
#pragma unroll
    for (int i = 0; i < 4; i++) {
        float4 w = { o[i][0], o[i][1], o[i][2], o[i][3] };
        *(float4*)(g_pacc + pb + (tm * 4 + i) * 64 + tn * 4) = w;
    }
    if (tn == 0) {
        int mb = (bh * NSPL + sp) * 64 + tm * 4;
#pragma unroll
        for (int i = 0; i < 4; i++) g_psum[mb + i] = gsum[i];
    }
}

// ===== combine partials -> k3V (normalized), then W = inv @ k3V ===========
__global__ void __launch_bounds__(256) k3v_combine()
{
    __shared__ float k3s[4096];    // [j][d]
    __shared__ float invs[4096];   // [m][j]
    __shared__ float inv_s[64];
    int bh = blockIdx.x, tid = threadIdx.x;
    size_t lb = (size_t)bh * 4096;

    if (tid < 64) {
        float tot = 0.f;
#pragma unroll
        for (int s2 = 0; s2 < NSPL; s2++) tot += g_psum[(bh * NSPL + s2) * 64 + tid];
        inv_s[tid] = 1.0f / tot;
    }
    for (int e = tid * 4; e < 4096; e += 1024)
        *(float4*)(invs + e) = *(const float4*)(g_inv + lb + e);
    __syncthreads();

    size_t pb = (size_t)bh * NSPL * 4096;
    for (int e = tid * 4; e < 4096; e += 1024) {
        int m = e >> 6;
        float4 o = make_float4(0.f, 0.f, 0.f, 0.f);
#pragma unroll
        for (int s2 = 0; s2 < NSPL; s2++) {
            float4 a = *(const float4*)(g_pacc + pb + s2*4096 + e);
            o.x += a.x; o.y += a.y; o.z += a.z; o.w += a.w;
        }
        float iv = inv_s[m];
        o.x *= iv; o.y *= iv; o.z *= iv; o.w *= iv;
        *(float4*)(k3s + e) = o;
    }
    __syncthreads();

    // W[i][q*16..+15] = sum_k invs[i][k] * k3s[k][...]
    int i = tid >> 2, q = tid & 3;
    float a[16];
#pragma unroll
    for (int j = 0; j < 16; j++) a[j] = 0.f;
    const float* Xi = invs + i * 64;
#pragma unroll
    for (int k = 0; k < 64; k += 4) {
        float4 xv = *(const float4*)(Xi + k);
        float xs[4] = {xv.x, xv.y, xv.z, xv.w};
#pragma unroll
        for (int kk = 0; kk < 4; kk++) {
            const float* Yr = k3s + (k + kk) * 64 + q * 16;
            float4 y0 = *(const float4*)(Yr);
            float4 y1 = *(const float4*)(Yr + 4);
            float4 y2 = *(const float4*)(Yr + 8);
            float4 y3 = *(const float4*)(Yr + 12);
            float xk = xs[kk];
            a[0]  = fmaf(xk, y0.x, a[0]);  a[1]  = fmaf(xk, y0.y, a[1]);
            a[2]  = fmaf(xk, y0.z, a[2]);  a[3]  = fmaf(xk, y0.w, a[3]);
            a[4]  = fmaf(xk, y1.x, a[4]);  a[5]  = fmaf(xk, y1.y, a[5]);
            a[6]  = fmaf(xk, y1.z, a[6]);  a[7]  = fmaf(xk, y1.w, a[7]);
            a[8]  = fmaf(xk, y2.x, a[8]);  a[9]  = fmaf(xk, y2.y, a[9]);
            a[10] = fmaf(xk, y2.z, a[10]); a[11] = fmaf(xk, y2.w, a[11]);
            a[12] = fmaf(xk, y3.x, a[12]); a[13] = fmaf(xk, y3.y, a[13]);
            a[14] = fmaf(xk, y3.z, a[14]); a[15] = fmaf(xk, y3.w, a[15]);
        }
    }
#pragma unroll
    for (int j = 0; j < 16; j += 4) {
        float4 w = { a[j], a[j+1], a[j+2], a[j+3] };
        *(float4*)(g_W + lb + i * 64 + q * 16 + j) = w;
    }
}

// ===== kernel1: softmax(Q·Kl^T) @ W, 4 row-batches per block ===============
// smem 51200B: Qt/Ps alias [4352] | Kls[4352] | Ws[4096]
__global__ void __launch_bounds__(256) k1_kernel()
{
    extern __shared__ float s[];
    float* Qt  = s;                   // [d][n] 68 (dead after scores)
    float* Ps  = s;                   // [m][n] 68 (aliases Qt)
    float* Kls = s + 4352;            // [d][m] 68
    float* Ws  = s + 8704;            // [m][d] 64
    int bh = blockIdx.x;
    int b = bh / HC, h = bh - b * HC;
    int tid = threadIdx.x, tn = tid >> 4, tc = tid & 15;
    size_t lb = (size_t)bh * 4096;

    for (int f = tid; f < 1024; f += 256) {
        int r = f >> 4, dg = (f & 15) * 4;
        float4 kl = *(const float4*)(g_Kl + lb + r * 64 + dg);
        Kls[(dg+0)*68+r] = kl.x; Kls[(dg+1)*68+r] = kl.y;
        Kls[(dg+2)*68+r] = kl.z; Kls[(dg+3)*68+r] = kl.w;
        *(float4*)(Ws + r * 64 + dg) = *(const float4*)(g_W + lb + r * 64 + dg);
    }

    for (int bat = 0; bat < 4; bat++) {
        int n0 = blockIdx.y * 256 + bat * 64;
        size_t qbase = ((size_t)bh * NC + n0) * DC;
        __syncthreads();              // prev PW done reading Ps; Kls/Ws visible
        for (int f = tid; f < 1024; f += 256) {
            int r = f >> 4, dg = (f & 15) * 4;
            float4 q = *(const float4*)(g_Q + qbase + r * 64 + dg);
            Qt[(dg+0)*68+r] = q.x; Qt[(dg+1)*68+r] = q.y;
            Qt[(dg+2)*68+r] = q.z; Qt[(dg+3)*68+r] = q.w;
        }
        __syncthreads();

        float sc[4][4];
#pragma unroll
        for (int i = 0; i < 4; i++)
#pragma unroll
            for (int j = 0; j < 4; j++) sc[i][j] = 0.f;
#pragma unroll 8
        for (int d = 0; d < 64; d++) {
            float4 q = *(const float4*)(Qt + d * 68 + tn * 4);
            float4 k = *(const float4*)(Kls + d * 68 + tc * 4);
            float qa[4] = {q.x,q.y,q.z,q.w}, ka[4] = {k.x,k.y,k.z,k.w};
#pragma unroll
            for (int i = 0; i < 4; i++)
#pragma unroll
                for (int j = 0; j < 4; j++) sc[i][j] = fmaf(qa[i], ka[j], sc[i][j]);
        }
        __syncthreads();              // all reads of Qt done

#pragma unroll
        for (int i = 0; i < 4; i++) {
            float p[4], ts = 0.f;
#pragma unroll
            for (int j = 0; j < 4; j++) { p[j] = __expf(sc[i][j]); ts += p[j]; }
            ts += __shfl_xor_sync(~0u, ts, 1);
            ts += __shfl_xor_sync(~0u, ts, 2);
            ts += __shfl_xor_sync(~0u, ts, 4);
            ts += __shfl_xor_sync(~0u, ts, 8);
            float is = 1.0f / ts;
#pragma unroll
            for (int j = 0; j < 4; j++)
                Ps[(tc * 4 + j) * 68 + tn * 4 + i] = p[j] * is;
        }
        __syncthreads();              // Ps visible

        float o[4][4];
#pragma unroll
        for (int i = 0; i < 4; i++)
#pragma unroll
            for (int j = 0; j < 4; j++) o[i][j] = 0.f;
#pragma unroll 8
        for (int m = 0; m < 64; m++) {
            float4 p = *(const float4*)(Ps + m * 68 + tn * 4);
            float4 w4 = *(const float4*)(Ws + m * 64 + tc * 4);
            float pa[4] = {p.x,p.y,p.z,p.w}, wa[4] = {w4.x,w4.y,w4.z,w4.w};
#pragma unroll
            for (int i = 0; i < 4; i++)
#pragma unroll
                for (int j = 0; j < 4; j++) o[i][j] = fmaf(pa[i], wa[j], o[i][j]);
        }
#pragma unroll
        for (int i = 0; i < 4; i++) {
            int n = n0 + tn * 4 + i;
            float4 w = { o[i][0], o[i][1], o[i][2], o[i][3] };
            *(float4*)(g_SV + ((size_t)b * NC + n) * CC + h * 64 + tc * 4) = w;
        }
    }
}

// ===================== launcher =====================
extern "C" void kernel_launch(void* const* d_in, const int* in_sizes, int n_in,
                              void* d_out, int out_size)
{
    (void)in_sizes; (void)n_in; (void)out_size;
    const float* x      = (const float*)d_in[0];
    const float* w_qkv  = (const float*)d_in[1];
    const float* w_proj = (const float*)d_in[2];
    const float* b_proj = (const float*)d_in[3];
    float* out = (float*)d_out;

    cudaFuncSetAttribute(mma_gemm<0>, cudaFuncAttributeMaxDynamicSharedMemorySize, 73728);
    cudaFuncSetAttribute(mma_gemm<1>, cudaFuncAttributeMaxDynamicSharedMemorySize, 73728);
    cudaFuncSetAttribute(inv_kernel, cudaFuncAttributeMaxDynamicSharedMemorySize, 5*4096*4);
    cudaFuncSetAttribute(k3v_part,   cudaFuncAttributeMaxDynamicSharedMemorySize, 51200);
    cudaFuncSetAttribute(k1_kernel,  cudaFuncAttributeMaxDynamicSharedMemorySize, 51200);

    mma_gemm<0><<<dim3(18, 256), 256, 73728>>>(x, w_qkv, nullptr, nullptr);
    landmarks_kernel<<<BHC * MC, 64>>>();
    inv_kernel<<<BHC, 256, 5*4096*4>>>();
    k3v_part<<<dim3(BHC, NSPL), 256, 51200>>>();
    k3v_combine<<<BHC, 256>>>();
    k1_kernel<<<dim3(BHC, 16), 256, 51200>>>();
    mma_gemm<1><<<dim3(6, 256), 256, 73728>>>(nullptr, w_proj, out, b_proj);
}